// round 1
// baseline (speedup 1.0000x reference)
#include <cuda_runtime.h>
#include <math.h>

#define WINDOW    128
#define EDIM      64      // head dim
#define KTOT      128     // concat [q | q_rot] feature dim
#define JW        256     // keys per window (prev + cur)
#define KC        16      // K-chunk for GEMM1 staging
#define NTHREADS  512

// smem layout (floats):
//   S  : 128*256 = 32768   (P matrix after softmax)
//   Vs : 256*64  = 16384
//   As : 128*16  =  2048
//   Bs : 16*256  =  4096
// total 55296 floats = 221184 bytes
#define SMEM_BYTES 221184

__global__ __launch_bounds__(NTHREADS, 1)
void local_attn_kernel(const float* __restrict__ q,
                       const float* __restrict__ k,
                       const float* __restrict__ qr,
                       const float* __restrict__ kr,
                       const float* __restrict__ v,
                       float* __restrict__ out,
                       int T)
{
    extern __shared__ float sm[];
    float* S  = sm;                 // [128][256]
    float* Vs = sm + 32768;         // [256][64]
    float* As = Vs + 16384;         // [128][16]
    float* Bs = As + 2048;          // [16][256]  (transposed: [kc][j])

    const int w    = blockIdx.x;            // window index
    const int b    = blockIdx.y;            // merged batch index
    const int tid  = threadIdx.x;
    const int lane = tid & 31;
    const int wy   = tid >> 5;               // warp id 0..15 -> rows wy*8..wy*8+7

    const long base  = (long)b * T * EDIM;
    const int  qrow0 = w * WINDOW;
    const int  krow0 = w * WINDOW - WINDOW;   // key j -> global row krow0 + j

    // ---- load V tile [256][64] into smem (zeros for padded rows) ----
    #pragma unroll
    for (int it = 0; it < 8; ++it) {
        int f    = tid + it * NTHREADS;   // 0..4095 float4s
        int rowV = f >> 4;                // /16
        int c4   = f & 15;
        int g    = krow0 + rowV;
        float4 val = make_float4(0.f, 0.f, 0.f, 0.f);
        if (g >= 0) val = *(const float4*)(v + base + (long)g * EDIM + c4 * 4);
        *(float4*)(Vs + rowV * EDIM + c4 * 4) = val;
    }

    // ---- GEMM1: S = [Q|Qrot] * [K|Krot]^T, register tile 8x8 per lane ----
    float s[8][8];
    #pragma unroll
    for (int r = 0; r < 8; ++r)
        #pragma unroll
        for (int c = 0; c < 8; ++c) s[r][c] = 0.f;

    for (int ch = 0; ch < 8; ++ch) {
        const int kk0 = ch * KC;
        const float* Asrc = (kk0 < EDIM) ? q : qr;
        const float* Bsrc = (kk0 < EDIM) ? k : kr;
        const int koff = kk0 & (EDIM - 1);

        __syncthreads();   // protect previous-iter smem reads (and V stores on iter 0)

        // A tile: 128x16 -> 512 float4, one per thread
        {
            int rowA = tid >> 2;
            int c4   = tid & 3;
            float4 val = *(const float4*)(Asrc + base + (long)(qrow0 + rowA) * EDIM + koff + c4 * 4);
            *(float4*)(As + rowA * KC + c4 * 4) = val;
        }
        // B tile: 256x16 -> 1024 float4, two per thread, stored transposed Bs[kc][j]
        #pragma unroll
        for (int it = 0; it < 2; ++it) {
            int f    = tid + it * NTHREADS;
            int rowB = f >> 2;
            int c4   = f & 3;
            int g    = krow0 + rowB;
            float4 val = make_float4(0.f, 0.f, 0.f, 0.f);
            if (g >= 0) val = *(const float4*)(Bsrc + base + (long)g * EDIM + koff + c4 * 4);
            Bs[(c4 * 4 + 0) * JW + rowB] = val.x;
            Bs[(c4 * 4 + 1) * JW + rowB] = val.y;
            Bs[(c4 * 4 + 2) * JW + rowB] = val.z;
            Bs[(c4 * 4 + 3) * JW + rowB] = val.w;
        }
        __syncthreads();

        #pragma unroll
        for (int kc = 0; kc < KC; ++kc) {
            float a[8];
            #pragma unroll
            for (int r = 0; r < 8; ++r) a[r] = As[(wy * 8 + r) * KC + kc];  // warp-uniform broadcast
            float4 b0 = *(float4*)(Bs + kc * JW + lane * 8);
            float4 b1 = *(float4*)(Bs + kc * JW + lane * 8 + 4);
            float bb[8] = {b0.x, b0.y, b0.z, b0.w, b1.x, b1.y, b1.z, b1.w};
            #pragma unroll
            for (int r = 0; r < 8; ++r)
                #pragma unroll
                for (int c = 0; c < 8; ++c)
                    s[r][c] = fmaf(a[r], bb[c], s[r][c]);
        }
    }

    // ---- mask + softmax (registers + warp shuffles; row == one warp) ----
    const float scale = 0.125f;   // 64^{-1/2}
    const float NEG   = -1e30f;
    const bool  w0    = (w == 0);
    float lrow[8];

    #pragma unroll
    for (int r = 0; r < 8; ++r) {
        const int i = wy * 8 + r;
        float m = NEG;
        #pragma unroll
        for (int c = 0; c < 8; ++c) {
            int j = lane * 8 + c;
            float val = s[r][c] * scale;
            bool mask = (j > i + 128) | (w0 & (j < 128));
            val = mask ? NEG : val;
            s[r][c] = val;
            m = fmaxf(m, val);
        }
        #pragma unroll
        for (int o = 16; o > 0; o >>= 1) m = fmaxf(m, __shfl_xor_sync(0xffffffffu, m, o));
        float lsum = 0.f;
        #pragma unroll
        for (int c = 0; c < 8; ++c) {
            float p = __expf(s[r][c] - m);
            s[r][c] = p;
            lsum += p;
        }
        #pragma unroll
        for (int o = 16; o > 0; o >>= 1) lsum += __shfl_xor_sync(0xffffffffu, lsum, o);
        lrow[r] = lsum;
    }

    // ---- write unnormalized P to smem ----
    #pragma unroll
    for (int r = 0; r < 8; ++r) {
        *(float4*)(S + (wy * 8 + r) * JW + lane * 8)     = make_float4(s[r][0], s[r][1], s[r][2], s[r][3]);
        *(float4*)(S + (wy * 8 + r) * JW + lane * 8 + 4) = make_float4(s[r][4], s[r][5], s[r][6], s[r][7]);
    }
    __syncthreads();

    // ---- GEMM2: O = P * V. Lane owns output cols {2*lane, 2*lane+1} ----
    float o0[8], o1[8];
    #pragma unroll
    for (int r = 0; r < 8; ++r) { o0[r] = 0.f; o1[r] = 0.f; }

    #pragma unroll 4
    for (int kk = 0; kk < JW; ++kk) {
        float2 bv = *(const float2*)(Vs + kk * EDIM + lane * 2);
        #pragma unroll
        for (int r = 0; r < 8; ++r) {
            float a = S[(wy * 8 + r) * JW + kk];   // warp-uniform broadcast
            o0[r] = fmaf(a, bv.x, o0[r]);
            o1[r] = fmaf(a, bv.y, o1[r]);
        }
    }

    // ---- epilogue: normalize and store ----
    #pragma unroll
    for (int r = 0; r < 8; ++r) {
        int i = wy * 8 + r;
        float inv = 1.0f / lrow[r];
        float2 res = make_float2(o0[r] * inv, o1[r] * inv);
        *(float2*)(out + base + (long)(qrow0 + i) * EDIM + lane * 2) = res;
    }
}

extern "C" void kernel_launch(void* const* d_in, const int* in_sizes, int n_in,
                              void* d_out, int out_size)
{
    const float* q  = (const float*)d_in[0];
    const float* k  = (const float*)d_in[1];
    const float* qr = (const float*)d_in[2];
    const float* kr = (const float*)d_in[3];
    const float* v  = (const float*)d_in[4];
    float* out      = (float*)d_out;

    const int T = 4096;
    const int total = in_sizes[0];           // 2*16*4096*64
    const int Bm = total / (T * EDIM);       // 32 merged batch
    const int W  = T / WINDOW;               // 32 windows

    cudaFuncSetAttribute(local_attn_kernel,
                         cudaFuncAttributeMaxDynamicSharedMemorySize, SMEM_BYTES);

    dim3 grid(W, Bm);
    local_attn_kernel<<<grid, NTHREADS, SMEM_BYTES>>>(q, k, qr, kr, v, out, T);
}

// round 3
// speedup vs baseline: 2.9550x; 2.9550x over previous
#include <cuda_runtime.h>
#include <cuda_bf16.h>
#include <cstdint>

#define EDIM  64
#define NTH   256

#define QH 0
#define QL 32768
#define KH 65536
#define KL 98304
#define VH 131072
#define VL 147456
#define SMEM_BYTES 163840

__device__ __forceinline__ uint32_t smem_u32(const void* p) {
    uint32_t a;
    asm("{ .reg .u64 t; cvta.to.shared.u64 t, %1; cvt.u32.u64 %0, t; }" : "=r"(a) : "l"(p));
    return a;
}
__device__ __forceinline__ void ldsm4(uint32_t* r, uint32_t addr) {
    asm volatile("ldmatrix.sync.aligned.m8n8.x4.shared.b16 {%0,%1,%2,%3}, [%4];"
        : "=r"(r[0]), "=r"(r[1]), "=r"(r[2]), "=r"(r[3]) : "r"(addr));
}
__device__ __forceinline__ void ldsm4t(uint32_t* r, uint32_t addr) {
    asm volatile("ldmatrix.sync.aligned.m8n8.x4.trans.shared.b16 {%0,%1,%2,%3}, [%4];"
        : "=r"(r[0]), "=r"(r[1]), "=r"(r[2]), "=r"(r[3]) : "r"(addr));
}
__device__ __forceinline__ void mma16816(float* d, const uint32_t* a, uint32_t b0, uint32_t b1) {
    asm volatile("mma.sync.aligned.m16n8k16.row.col.f32.bf16.bf16.f32 "
        "{%0,%1,%2,%3}, {%4,%5,%6,%7}, {%8,%9}, {%0,%1,%2,%3};"
        : "+f"(d[0]), "+f"(d[1]), "+f"(d[2]), "+f"(d[3])
        : "r"(a[0]), "r"(a[1]), "r"(a[2]), "r"(a[3]), "r"(b0), "r"(b1));
}
__device__ __forceinline__ void cvt_split(float4 v, uint2& hi, uint2& lo) {
    __nv_bfloat162 h0 = __floats2bfloat162_rn(v.x, v.y);
    __nv_bfloat162 h1 = __floats2bfloat162_rn(v.z, v.w);
    __nv_bfloat162 l0 = __floats2bfloat162_rn(v.x - __bfloat162float(h0.x),
                                              v.y - __bfloat162float(h0.y));
    __nv_bfloat162 l1 = __floats2bfloat162_rn(v.z - __bfloat162float(h1.x),
                                              v.w - __bfloat162float(h1.y));
    hi = make_uint2(*(uint32_t*)&h0, *(uint32_t*)&h1);
    lo = make_uint2(*(uint32_t*)&l0, *(uint32_t*)&l1);
}

__global__ __launch_bounds__(NTH, 1)
void local_attn_mma(const float* __restrict__ q,  const float* __restrict__ k,
                    const float* __restrict__ qr, const float* __restrict__ kr,
                    const float* __restrict__ v,  float* __restrict__ out, int T)
{
    extern __shared__ char sm[];
    const uint32_t sb = smem_u32(sm);
    const int tid  = threadIdx.x;
    const int wid  = tid >> 5;
    const int lane = tid & 31;
    const int w    = blockIdx.x;
    const int b    = blockIdx.y;

    const long base  = (long)b * T * EDIM;
    const int  qrow0 = w * 128;

    // ---- load Q [128 rows][128 f] -> QH/QL, swizzled ----
    #pragma unroll
    for (int it = 0; it < 16; ++it) {
        int idx = tid + it * NTH;
        int row = idx >> 5, f4 = idx & 31, f = f4 * 4;
        const float* src = (f < 64) ? q : qr;
        float4 val = *(const float4*)(src + base + (long)(qrow0 + row) * EDIM + (f & 63));
        uint2 hi, lo; cvt_split(val, hi, lo);
        uint32_t off = (uint32_t)(row * 256 + (((f4 >> 1) ^ (row & 7)) << 4) + (f4 & 1) * 8);
        *(uint2*)(sm + QH + off) = hi;
        *(uint2*)(sm + QL + off) = lo;
    }

    const int mrow  = lane >> 2;
    const int cb    = (lane & 3) * 2;
    const int irow0 = wid * 16 + mrow;
    const int irow1 = irow0 + 8;
    const int tt    = lane >> 3, rr = lane & 7;

    float mx0 = -1e30f, mx1 = -1e30f, l0 = 0.f, l1 = 0.f;
    float o[8][4];
    #pragma unroll
    for (int e = 0; e < 8; ++e) { o[e][0]=0.f; o[e][1]=0.f; o[e][2]=0.f; o[e][3]=0.f; }

    const int jb0 = (w == 0) ? 1 : 0;
    for (int jb = jb0; jb < 2; ++jb) {
        __syncthreads();
        const long kbase = base + (long)((w - 1 + jb) * 128) * EDIM;
        #pragma unroll
        for (int it = 0; it < 16; ++it) {
            int idx = tid + it * NTH;
            int row = idx >> 5, f4 = idx & 31, f = f4 * 4;
            const float* src = (f < 64) ? k : kr;
            float4 val = *(const float4*)(src + kbase + (long)row * EDIM + (f & 63));
            uint2 hi, lo; cvt_split(val, hi, lo);
            uint32_t off = (uint32_t)(row * 256 + (((f4 >> 1) ^ (row & 7)) << 4) + (f4 & 1) * 8);
            *(uint2*)(sm + KH + off) = hi;
            *(uint2*)(sm + KL + off) = lo;
        }
        #pragma unroll
        for (int it = 0; it < 8; ++it) {
            int idx = tid + it * NTH;
            int row = idx >> 4, f4 = idx & 15;
            float4 val = *(const float4*)(v + kbase + (long)row * EDIM + f4 * 4);
            uint2 hi, lo; cvt_split(val, hi, lo);
            uint32_t off = (uint32_t)(row * 128 + (((f4 >> 1) ^ (row & 7)) << 4) + (f4 & 1) * 8);
            *(uint2*)(sm + VH + off) = hi;
            *(uint2*)(sm + VL + off) = lo;
        }
        __syncthreads();

        float s[16][4];
        #pragma unroll
        for (int nt = 0; nt < 16; ++nt) { s[nt][0]=0.f; s[nt][1]=0.f; s[nt][2]=0.f; s[nt][3]=0.f; }

        #pragma unroll 1
        for (int kc = 0; kc < 8; ++kc) {
            int arow = wid * 16 + ((tt & 1) << 3) + rr;
            int ac16 = 2 * kc + (tt >> 1);
            uint32_t aoff = (uint32_t)(arow * 256 + ((ac16 ^ (arow & 7)) << 4));
            uint32_t ah[4], al[4];
            ldsm4(ah, sb + QH + aoff);
            ldsm4(al, sb + QL + aoff);
            #pragma unroll
            for (int np = 0; np < 8; ++np) {
                int brow = np * 16 + ((tt >> 1) << 3) + rr;
                int bc16 = 2 * kc + (tt & 1);
                uint32_t boff = (uint32_t)(brow * 256 + ((bc16 ^ (brow & 7)) << 4));
                uint32_t bh[4], bl[4];
                ldsm4(bh, sb + KH + boff);
                ldsm4(bl, sb + KL + boff);
                mma16816(s[2*np],   ah, bh[0], bh[1]);
                mma16816(s[2*np+1], ah, bh[2], bh[3]);
                mma16816(s[2*np],   ah, bl[0], bl[1]);
                mma16816(s[2*np+1], ah, bl[2], bl[3]);
                mma16816(s[2*np],   al, bh[0], bh[1]);
                mma16816(s[2*np+1], al, bh[2], bh[3]);
            }
        }

        const bool causal = (jb == 1);
        float rm0 = -1e30f, rm1 = -1e30f;
        #pragma unroll
        for (int nt = 0; nt < 16; ++nt) {
            int c0 = nt * 8 + cb;
            #pragma unroll
            for (int cc = 0; cc < 2; ++cc) {
                float v0 = s[nt][cc]     * 0.125f;
                float v1 = s[nt][2 + cc] * 0.125f;
                if (causal && (c0 + cc > irow0)) v0 = -1e30f;
                if (causal && (c0 + cc > irow1)) v1 = -1e30f;
                s[nt][cc]     = v0;
                s[nt][2 + cc] = v1;
                rm0 = fmaxf(rm0, v0);
                rm1 = fmaxf(rm1, v1);
            }
        }
        rm0 = fmaxf(rm0, __shfl_xor_sync(0xffffffffu, rm0, 1));
        rm0 = fmaxf(rm0, __shfl_xor_sync(0xffffffffu, rm0, 2));
        rm1 = fmaxf(rm1, __shfl_xor_sync(0xffffffffu, rm1, 1));
        rm1 = fmaxf(rm1, __shfl_xor_sync(0xffffffffu, rm1, 2));

        float mn0 = fmaxf(mx0, rm0), mn1 = fmaxf(mx1, rm1);
        float sf0 = __expf(mx0 - mn0), sf1 = __expf(mx1 - mn1);
        mx0 = mn0; mx1 = mn1;
        l0 *= sf0; l1 *= sf1;
        #pragma unroll
        for (int e = 0; e < 8; ++e) {
            o[e][0] *= sf0; o[e][1] *= sf0;
            o[e][2] *= sf1; o[e][3] *= sf1;
        }

        uint32_t ph[32], pl[32];
        #pragma unroll
        for (int nt = 0; nt < 16; ++nt) {
            float p00 = __expf(s[nt][0] - mx0);
            float p01 = __expf(s[nt][1] - mx0);
            float p10 = __expf(s[nt][2] - mx1);
            float p11 = __expf(s[nt][3] - mx1);
            l0 += p00 + p01;
            l1 += p10 + p11;
            __nv_bfloat162 h0 = __floats2bfloat162_rn(p00, p01);
            __nv_bfloat162 h1 = __floats2bfloat162_rn(p10, p11);
            __nv_bfloat162 e0 = __floats2bfloat162_rn(p00 - __bfloat162float(h0.x),
                                                      p01 - __bfloat162float(h0.y));
            __nv_bfloat162 e1 = __floats2bfloat162_rn(p10 - __bfloat162float(h1.x),
                                                      p11 - __bfloat162float(h1.y));
            ph[2*nt]   = *(uint32_t*)&h0;
            ph[2*nt+1] = *(uint32_t*)&h1;
            pl[2*nt]   = *(uint32_t*)&e0;
            pl[2*nt+1] = *(uint32_t*)&e1;
        }

        #pragma unroll
        for (int jc = 0; jc < 8; ++jc) {
            const uint32_t* Ah = ph + 4 * jc;
            const uint32_t* Al = pl + 4 * jc;
            #pragma unroll
            for (int ep = 0; ep < 4; ++ep) {
                int vrow = jc * 16 + ((tt & 1) << 3) + rr;
                int vc16 = ep * 2 + (tt >> 1);
                uint32_t voff = (uint32_t)(vrow * 128 + ((vc16 ^ (vrow & 7)) << 4));
                uint32_t vh[4], vl[4];
                ldsm4t(vh, sb + VH + voff);
                ldsm4t(vl, sb + VL + voff);
                mma16816(o[2*ep],   Ah, vh[0], vh[1]);
                mma16816(o[2*ep+1], Ah, vh[2], vh[3]);
                mma16816(o[2*ep],   Ah, vl[0], vl[1]);
                mma16816(o[2*ep+1], Ah, vl[2], vl[3]);
                mma16816(o[2*ep],   Al, vh[0], vh[1]);
                mma16816(o[2*ep+1], Al, vh[2], vh[3]);
            }
        }
    }

    l0 += __shfl_xor_sync(0xffffffffu, l0, 1);
    l0 += __shfl_xor_sync(0xffffffffu, l0, 2);
    l1 += __shfl_xor_sync(0xffffffffu, l1, 1);
    l1 += __shfl_xor_sync(0xffffffffu, l1, 2);
    float inv0 = 1.0f / l0, inv1 = 1.0f / l1;
    #pragma unroll
    for (int e = 0; e < 8; ++e) {
        int col = e * 8 + cb;
        *(float2*)(out + base + (long)(qrow0 + irow0) * EDIM + col) =
            make_float2(o[e][0] * inv0, o[e][1] * inv0);
        *(float2*)(out + base + (long)(qrow0 + irow1) * EDIM + col) =
            make_float2(o[e][2] * inv1, o[e][3] * inv1);
    }
}

extern "C" void kernel_launch(void* const* d_in, const int* in_sizes, int n_in,
                              void* d_out, int out_size)
{
    const float* q  = (const float*)d_in[0];
    const float* k  = (const float*)d_in[1];
    const float* qr = (const float*)d_in[2];
    const float* kr = (const float*)d_in[3];
    const float* v  = (const float*)d_in[4];
    float* out      = (float*)d_out;

    const int T  = 4096;
    const int Bm = in_sizes[0] / (T * EDIM);
    const int W  = T / 128;

    cudaFuncSetAttribute(local_attn_mma, cudaFuncAttributeMaxDynamicSharedMemorySize, SMEM_BYTES);
    dim3 grid(W, Bm);
    local_attn_mma<<<grid, NTH, SMEM_BYTES>>>(q, k, qr, kr, v, out, T);
}

// round 4
// speedup vs baseline: 3.3219x; 1.1242x over previous
#include <cuda_runtime.h>
#include <cuda_fp16.h>
#include <cstdint>

#define EDIM 64
#define NTH  256

// smem layout (bytes)
#define QH   0        // 128x128 fp16 (Q hi)           32768
#define KH   32768    // 128x128 fp16 (K hi)           32768
#define KL   65536    // 128x128 fp16 (K lo)           32768
#define VH   98304    // 128x64  fp16 (V hi)           16384
#define VL   114688   // 128x64  fp16 (V lo)           16384
#define RAWK 131072   // 128x128 fp32 raw staging      65536
#define RAWV 196608   // 128x64  fp32 raw staging      32768
#define SMEM_BYTES 229376

__device__ __forceinline__ uint32_t smem_u32(const void* p) {
    uint32_t a;
    asm("{ .reg .u64 t; cvta.to.shared.u64 t, %1; cvt.u32.u64 %0, t; }" : "=r"(a) : "l"(p));
    return a;
}
__device__ __forceinline__ void ldsm4(uint32_t* r, uint32_t addr) {
    asm volatile("ldmatrix.sync.aligned.m8n8.x4.shared.b16 {%0,%1,%2,%3}, [%4];"
        : "=r"(r[0]), "=r"(r[1]), "=r"(r[2]), "=r"(r[3]) : "r"(addr));
}
__device__ __forceinline__ void ldsm4t(uint32_t* r, uint32_t addr) {
    asm volatile("ldmatrix.sync.aligned.m8n8.x4.trans.shared.b16 {%0,%1,%2,%3}, [%4];"
        : "=r"(r[0]), "=r"(r[1]), "=r"(r[2]), "=r"(r[3]) : "r"(addr));
}
__device__ __forceinline__ void mma16816(float* d, const uint32_t* a, uint32_t b0, uint32_t b1) {
    asm volatile("mma.sync.aligned.m16n8k16.row.col.f32.f16.f16.f32 "
        "{%0,%1,%2,%3}, {%4,%5,%6,%7}, {%8,%9}, {%0,%1,%2,%3};"
        : "+f"(d[0]), "+f"(d[1]), "+f"(d[2]), "+f"(d[3])
        : "r"(a[0]), "r"(a[1]), "r"(a[2]), "r"(a[3]), "r"(b0), "r"(b1));
}
#define CP_ASYNC16(dst, src) asm volatile("cp.async.cg.shared.global [%0], [%1], 16;" :: "r"(dst), "l"(src) : "memory")
#define CP_COMMIT()          asm volatile("cp.async.commit_group;" ::: "memory")
#define CP_WAIT0()           asm volatile("cp.async.wait_group 0;" ::: "memory")

// fp32x4 -> fp16 hi + fp16 residual(lo)
__device__ __forceinline__ void cvt_splith(float4 v, uint2& hi, uint2& lo) {
    __half2 h0 = __floats2half2_rn(v.x, v.y);
    __half2 h1 = __floats2half2_rn(v.z, v.w);
    float rx = v.x - __half2float(__low2half(h0));
    float ry = v.y - __half2float(__high2half(h0));
    float rz = v.z - __half2float(__low2half(h1));
    float rw = v.w - __half2float(__high2half(h1));
    __half2 l0 = __floats2half2_rn(rx, ry);
    __half2 l1 = __floats2half2_rn(rz, rw);
    hi = make_uint2(*(uint32_t*)&h0, *(uint32_t*)&h1);
    lo = make_uint2(*(uint32_t*)&l0, *(uint32_t*)&l1);
}

__global__ __launch_bounds__(NTH, 1)
void local_attn_mma(const float* __restrict__ q,  const float* __restrict__ k,
                    const float* __restrict__ qr, const float* __restrict__ kr,
                    const float* __restrict__ v,  float* __restrict__ out, int T)
{
    extern __shared__ char sm[];
    const uint32_t sb = smem_u32(sm);
    const int tid  = threadIdx.x;
    const int wid  = tid >> 5;
    const int lane = tid & 31;
    const int w    = blockIdx.x;
    const int b    = blockIdx.y;

    const long base  = (long)b * T * EDIM;
    const int  qrow0 = w * 128;

    const int nb  = (w == 0) ? 1 : 2;      // key blocks to process
    const int kb0 = w - nb + 1;            // first key-block index (>= 0)

    // ---- prefetch raw K/V for first key block via cp.async ----
    {
        const long kbase = base + (long)(kb0 * 128) * EDIM;
        #pragma unroll
        for (int it = 0; it < 16; ++it) {
            int idx = tid + it * NTH;               // 0..4095
            int row = idx >> 5, c4 = idx & 31;
            const float* src = (c4 < 16) ? k : kr;
            CP_ASYNC16(sb + RAWK + idx * 16, src + kbase + (long)row * EDIM + (c4 & 15) * 4);
        }
        #pragma unroll
        for (int it = 0; it < 8; ++it) {
            int idx = tid + it * NTH;               // 0..2047
            int row = idx >> 4, c4 = idx & 15;
            CP_ASYNC16(sb + RAWV + idx * 16, v + kbase + (long)row * EDIM + c4 * 4);
        }
        CP_COMMIT();
    }

    // ---- load Q [128 rows][128 f] -> QH (hi only), swizzled ----
    #pragma unroll
    for (int it = 0; it < 16; ++it) {
        int idx = tid + it * NTH;
        int row = idx >> 5, f4 = idx & 31, f = f4 * 4;
        const float* src = (f < 64) ? q : qr;
        float4 val = *(const float4*)(src + base + (long)(qrow0 + row) * EDIM + (f & 63));
        __half2 h0 = __floats2half2_rn(val.x, val.y);
        __half2 h1 = __floats2half2_rn(val.z, val.w);
        uint2 hi = make_uint2(*(uint32_t*)&h0, *(uint32_t*)&h1);
        uint32_t off = (uint32_t)(row * 256 + (((f4 >> 1) ^ (row & 7)) << 4) + (f4 & 1) * 8);
        *(uint2*)(sm + QH + off) = hi;
    }

    const int mrow  = lane >> 2;
    const int cb    = (lane & 3) * 2;
    const int irow0 = wid * 16 + mrow;
    const int irow1 = irow0 + 8;
    const int tt    = lane >> 3, rr = lane & 7;

    float mx0 = -1e30f, mx1 = -1e30f, l0 = 0.f, l1 = 0.f;
    float o[8][4];
    #pragma unroll
    for (int e = 0; e < 8; ++e) { o[e][0]=0.f; o[e][1]=0.f; o[e][2]=0.f; o[e][3]=0.f; }

    for (int ib = 0; ib < nb; ++ib) {
        // ---- raw block ready; previous iteration's consumers done ----
        CP_WAIT0();
        __syncthreads();

        // ---- convert raw fp32 -> fp16 hi/lo, swizzled ----
        #pragma unroll
        for (int it = 0; it < 16; ++it) {
            int idx = tid + it * NTH;
            int row = idx >> 5, f4 = idx & 31;
            float4 val = *(const float4*)(sm + RAWK + idx * 16);
            uint2 hi, lo; cvt_splith(val, hi, lo);
            uint32_t off = (uint32_t)(row * 256 + (((f4 >> 1) ^ (row & 7)) << 4) + (f4 & 1) * 8);
            *(uint2*)(sm + KH + off) = hi;
            *(uint2*)(sm + KL + off) = lo;
        }
        #pragma unroll
        for (int it = 0; it < 8; ++it) {
            int idx = tid + it * NTH;
            int row = idx >> 4, f4 = idx & 15;
            float4 val = *(const float4*)(sm + RAWV + idx * 16);
            uint2 hi, lo; cvt_splith(val, hi, lo);
            uint32_t off = (uint32_t)(row * 128 + (((f4 >> 1) ^ (row & 7)) << 4) + (f4 & 1) * 8);
            *(uint2*)(sm + VH + off) = hi;
            *(uint2*)(sm + VL + off) = lo;
        }
        __syncthreads();

        // ---- prefetch next block (overlaps with compute below) ----
        if (ib + 1 < nb) {
            const long kbase = base + (long)((kb0 + ib + 1) * 128) * EDIM;
            #pragma unroll
            for (int it = 0; it < 16; ++it) {
                int idx = tid + it * NTH;
                int row = idx >> 5, c4 = idx & 31;
                const float* src = (c4 < 16) ? k : kr;
                CP_ASYNC16(sb + RAWK + idx * 16, src + kbase + (long)row * EDIM + (c4 & 15) * 4);
            }
            #pragma unroll
            for (int it = 0; it < 8; ++it) {
                int idx = tid + it * NTH;
                int row = idx >> 4, c4 = idx & 15;
                CP_ASYNC16(sb + RAWV + idx * 16, v + kbase + (long)row * EDIM + c4 * 4);
            }
            CP_COMMIT();
        }

        // ---- GEMM1: S[16 rows][128 j], fp16 2-term (ah*bh + ah*bl) ----
        float s[16][4];
        #pragma unroll
        for (int nt = 0; nt < 16; ++nt) { s[nt][0]=0.f; s[nt][1]=0.f; s[nt][2]=0.f; s[nt][3]=0.f; }

        #pragma unroll 1
        for (int kc = 0; kc < 8; ++kc) {
            int arow = wid * 16 + ((tt & 1) << 3) + rr;
            int ac16 = 2 * kc + (tt >> 1);
            uint32_t aoff = (uint32_t)(arow * 256 + ((ac16 ^ (arow & 7)) << 4));
            uint32_t ah[4];
            ldsm4(ah, sb + QH + aoff);
            #pragma unroll
            for (int np = 0; np < 8; ++np) {
                int brow = np * 16 + ((tt >> 1) << 3) + rr;
                int bc16 = 2 * kc + (tt & 1);
                uint32_t boff = (uint32_t)(brow * 256 + ((bc16 ^ (brow & 7)) << 4));
                uint32_t bh[4], bl[4];
                ldsm4(bh, sb + KH + boff);
                ldsm4(bl, sb + KL + boff);
                mma16816(s[2*np],   ah, bh[0], bh[1]);
                mma16816(s[2*np+1], ah, bh[2], bh[3]);
                mma16816(s[2*np],   ah, bl[0], bl[1]);
                mma16816(s[2*np+1], ah, bl[2], bl[3]);
            }
        }

        // ---- scale + mask + online softmax ----
        const bool causal = (ib == nb - 1);
        float rm0 = -1e30f, rm1 = -1e30f;
        #pragma unroll
        for (int nt = 0; nt < 16; ++nt) {
            int c0 = nt * 8 + cb;
            #pragma unroll
            for (int cc = 0; cc < 2; ++cc) {
                float v0 = s[nt][cc]     * 0.125f;
                float v1 = s[nt][2 + cc] * 0.125f;
                if (causal && (c0 + cc > irow0)) v0 = -1e30f;
                if (causal && (c0 + cc > irow1)) v1 = -1e30f;
                s[nt][cc]     = v0;
                s[nt][2 + cc] = v1;
                rm0 = fmaxf(rm0, v0);
                rm1 = fmaxf(rm1, v1);
            }
        }
        rm0 = fmaxf(rm0, __shfl_xor_sync(0xffffffffu, rm0, 1));
        rm0 = fmaxf(rm0, __shfl_xor_sync(0xffffffffu, rm0, 2));
        rm1 = fmaxf(rm1, __shfl_xor_sync(0xffffffffu, rm1, 1));
        rm1 = fmaxf(rm1, __shfl_xor_sync(0xffffffffu, rm1, 2));

        float mn0 = fmaxf(mx0, rm0), mn1 = fmaxf(mx1, rm1);
        float sf0 = __expf(mx0 - mn0), sf1 = __expf(mx1 - mn1);
        mx0 = mn0; mx1 = mn1;
        l0 *= sf0; l1 *= sf1;
        #pragma unroll
        for (int e = 0; e < 8; ++e) {
            o[e][0] *= sf0; o[e][1] *= sf0;
            o[e][2] *= sf1; o[e][3] *= sf1;
        }

        // ---- exp + pack P (fp16 hi only) ----
        uint32_t ph[32];
        #pragma unroll
        for (int nt = 0; nt < 16; ++nt) {
            float p00 = __expf(s[nt][0] - mx0);
            float p01 = __expf(s[nt][1] - mx0);
            float p10 = __expf(s[nt][2] - mx1);
            float p11 = __expf(s[nt][3] - mx1);
            l0 += p00 + p01;
            l1 += p10 + p11;
            __half2 h0 = __floats2half2_rn(p00, p01);
            __half2 h1 = __floats2half2_rn(p10, p11);
            ph[2*nt]   = *(uint32_t*)&h0;
            ph[2*nt+1] = *(uint32_t*)&h1;
        }

        // ---- GEMM2: O += P * V, fp16 2-term (ph*vh + ph*vl) ----
        #pragma unroll
        for (int jc = 0; jc < 8; ++jc) {
            const uint32_t* Ah = ph + 4 * jc;
            #pragma unroll
            for (int ep = 0; ep < 4; ++ep) {
                int vrow = jc * 16 + ((tt & 1) << 3) + rr;
                int vc16 = ep * 2 + (tt >> 1);
                uint32_t voff = (uint32_t)(vrow * 128 + ((vc16 ^ (vrow & 7)) << 4));
                uint32_t vh[4], vl[4];
                ldsm4t(vh, sb + VH + voff);
                ldsm4t(vl, sb + VL + voff);
                mma16816(o[2*ep],   Ah, vh[0], vh[1]);
                mma16816(o[2*ep+1], Ah, vh[2], vh[3]);
                mma16816(o[2*ep],   Ah, vl[0], vl[1]);
                mma16816(o[2*ep+1], Ah, vl[2], vl[3]);
            }
        }
    }

    // ---- epilogue ----
    l0 += __shfl_xor_sync(0xffffffffu, l0, 1);
    l0 += __shfl_xor_sync(0xffffffffu, l0, 2);
    l1 += __shfl_xor_sync(0xffffffffu, l1, 1);
    l1 += __shfl_xor_sync(0xffffffffu, l1, 2);
    float inv0 = 1.0f / l0, inv1 = 1.0f / l1;
    #pragma unroll
    for (int e = 0; e < 8; ++e) {
        int col = e * 8 + cb;
        *(float2*)(out + base + (long)(qrow0 + irow0) * EDIM + col) =
            make_float2(o[e][0] * inv0, o[e][1] * inv0);
        *(float2*)(out + base + (long)(qrow0 + irow1) * EDIM + col) =
            make_float2(o[e][2] * inv1, o[e][3] * inv1);
    }
}

extern "C" void kernel_launch(void* const* d_in, const int* in_sizes, int n_in,
                              void* d_out, int out_size)
{
    const float* q  = (const float*)d_in[0];
    const float* k  = (const float*)d_in[1];
    const float* qr = (const float*)d_in[2];
    const float* kr = (const float*)d_in[3];
    const float* v  = (const float*)d_in[4];
    float* out      = (float*)d_out;

    const int T  = 4096;
    const int Bm = in_sizes[0] / (T * EDIM);
    const int W  = T / 128;

    cudaFuncSetAttribute(local_attn_mma, cudaFuncAttributeMaxDynamicSharedMemorySize, SMEM_BYTES);
    dim3 grid(W, Bm);
    local_attn_mma<<<grid, NTH, SMEM_BYTES>>>(q, k, qr, kr, v, out, T);
}